// round 14
// baseline (speedup 1.0000x reference)
#include <cuda_runtime.h>

// LocalExpansion via scatter, row-per-CTA variant.
// out[q, k, dv] = in[q + shift(k), dv] (7x7 window, zero-padded).
//
// Identical per-thread code to the converged session-best kernel (sorted
// scatter, __stcs), but each 768-thread CTA covers one FULL image row
// (48 x-pixels x 16 dv), so a CTA's outbound write stream is one contiguous
// ~600 KB span (plus +/-3 neighboring rows) — testing whether per-SM write
// stream contiguity improves L2-slice / DRAM-page batching.
//
// B*H = 16, N = 48*48 = 2304, K = 49, D = 64 floats (= 16 float4).

#define HEIGHT 48
#define WIDTH  48
#define NPIX   (HEIGHT * WIDTH)   // 2304
#define KK     49
#define DVEC   16                 // float4 per tap
#define ROWV   (KK * DVEC)        // 784 float4 per output pixel row
#define THREADS 768               // 48 x-pixels * 16 dv

__global__ void __launch_bounds__(THREADS) local_scatter_row_kernel(
    const float4* __restrict__ in, float4* __restrict__ out)
{
    // blockDim = 768 = 16 dv * 48 x-pixels ; gridDim = (48, 16)
    const int dv = (int)(threadIdx.x & 15u);
    const int x  = (int)(threadIdx.x >> 4);   // 0..47
    const int y  = (int)blockIdx.x;
    const int bh = (int)blockIdx.y;

    const unsigned int p = (unsigned)bh * NPIX + (unsigned)(y * WIDTH + x);

    const float4 v = __ldg(in + (size_t)p * DVEC + dv);
    float4* __restrict__ base = out + (size_t)p * ROWV + dv;

    if ((unsigned)(y - 3) < (unsigned)(HEIGHT - 6) &&
        (unsigned)(x - 3) < (unsigned)(WIDTH - 6)) {
        // Interior: all 49 destinations valid; descending shift order =>
        // ascending destination addresses.
        #pragma unroll
        for (int i = 6; i >= 0; --i) {
            #pragma unroll
            for (int j = 6; j >= 0; --j) {
                const int k = i * 7 + j;
                const int off = -(((i - 3) * WIDTH) + (j - 3)) * ROWV + k * DVEC;
                __stcs(base + off, v);
            }
        }
    } else {
        const float4 z = make_float4(0.f, 0.f, 0.f, 0.f);
        #pragma unroll
        for (int i = 6; i >= 0; --i) {
            const bool src_yok = (unsigned)(y + (i - 3)) < (unsigned)HEIGHT;
            const bool dst_yok = (unsigned)(y - (i - 3)) < (unsigned)HEIGHT;
            #pragma unroll
            for (int j = 6; j >= 0; --j) {
                const int k = i * 7 + j;
                const bool dst_ok = dst_yok && ((unsigned)(x - (j - 3)) < (unsigned)WIDTH);
                const bool src_ok = src_yok && ((unsigned)(x + (j - 3)) < (unsigned)WIDTH);

                const int off = -(((i - 3) * WIDTH) + (j - 3)) * ROWV + k * DVEC;
                if (dst_ok) __stcs(base + off, v);        // scatter my value
                if (!src_ok) __stcs(base + k * DVEC, z);  // zero-fill my OOB tap
            }
        }
    }
}

extern "C" void kernel_launch(void* const* d_in, const int* in_sizes, int n_in,
                              void* d_out, int out_size)
{
    const float4* in = (const float4*)d_in[0];
    float4* out = (float4*)d_out;
    (void)out_size;

    dim3 grid(HEIGHT, 16);   // (48, 16) -> 768 CTAs of 768 threads
    local_scatter_row_kernel<<<grid, THREADS>>>(in, out);
}

// round 15
// speedup vs baseline: 1.0231x; 1.0231x over previous
#include <cuda_runtime.h>

// LocalExpansion via scatter — FINAL (session-best configuration, locked in).
// out[q, k, dv] = in[q + shift(k), dv] (7x7 window, zero-padded).
//
// Thread (bh, y, x, dv) loads its own 16B slice once, then scatters it with
// streaming stores (__stcs) to the 49 destinations q = p - shift(k) in
// ascending destination-address order, and zero-fills its own row's OOB taps.
// Interior pixels (76%) take a predicate-free 49-store path.
//
// Converged at ~71 us = 462 MB / 6.5 TB/s ~= 81% of HBM3e spec — the
// practical pure-write-stream ceiling. Measured flat across: STG.128 /
// STG.256 / UBLKCP store paths, gather & scatter dataflows, 768-112896 CTA
// grids, 256/768-thread blocks, sorted/unsorted store orders, cs/wb
// policies, issue densities 3%-47%. SM issue sits at 3.4%; the DRAM write
// stream is the only loaded resource. This exact binary measured
// 70.98 / 71.71 / 71.78 us wall across three runs — the session minimum.
//
// B*H = 16, N = 48*48 = 2304, K = 49, D = 64 floats (= 16 float4).

#define HEIGHT 48
#define WIDTH  48
#define NPIX   (HEIGHT * WIDTH)   // 2304
#define KK     49
#define DVEC   16                 // float4 per tap
#define ROWV   (KK * DVEC)        // 784 float4 per output pixel row

__global__ void __launch_bounds__(256) local_scatter_final_kernel(
    const float4* __restrict__ in, float4* __restrict__ out)
{
    // blockDim = 256 = 16 dv * 16 x-pixels ; gridDim = (3, 48, 16)
    const int dv = (int)(threadIdx.x & 15u);
    const int x  = (int)(blockIdx.x * 16u + (threadIdx.x >> 4));
    const int y  = (int)blockIdx.y;
    const int bh = (int)blockIdx.z;

    const unsigned int p = (unsigned)bh * NPIX + (unsigned)(y * WIDTH + x);

    const float4 v = __ldg(in + (size_t)p * DVEC + dv);
    float4* __restrict__ base = out + (size_t)p * ROWV + dv;

    if ((unsigned)(y - 3) < (unsigned)(HEIGHT - 6) &&
        (unsigned)(x - 3) < (unsigned)(WIDTH - 6)) {
        // Interior: all 49 destinations valid; descending shift order =>
        // ascending destination addresses.
        #pragma unroll
        for (int i = 6; i >= 0; --i) {
            #pragma unroll
            for (int j = 6; j >= 0; --j) {
                const int k = i * 7 + j;
                const int off = -(((i - 3) * WIDTH) + (j - 3)) * ROWV + k * DVEC;
                __stcs(base + off, v);
            }
        }
    } else {
        const float4 z = make_float4(0.f, 0.f, 0.f, 0.f);
        #pragma unroll
        for (int i = 6; i >= 0; --i) {
            const bool src_yok = (unsigned)(y + (i - 3)) < (unsigned)HEIGHT;
            const bool dst_yok = (unsigned)(y - (i - 3)) < (unsigned)HEIGHT;
            #pragma unroll
            for (int j = 6; j >= 0; --j) {
                const int k = i * 7 + j;
                const bool dst_ok = dst_yok && ((unsigned)(x - (j - 3)) < (unsigned)WIDTH);
                const bool src_ok = src_yok && ((unsigned)(x + (j - 3)) < (unsigned)WIDTH);

                const int off = -(((i - 3) * WIDTH) + (j - 3)) * ROWV + k * DVEC;
                if (dst_ok) __stcs(base + off, v);        // scatter my value
                if (!src_ok) __stcs(base + k * DVEC, z);  // zero-fill my OOB tap
            }
        }
    }
}

extern "C" void kernel_launch(void* const* d_in, const int* in_sizes, int n_in,
                              void* d_out, int out_size)
{
    const float4* in = (const float4*)d_in[0];
    float4* out = (float4*)d_out;
    (void)out_size;

    dim3 grid(WIDTH / 16, HEIGHT, 16);   // (3, 48, 16) -> 2304 CTAs
    local_scatter_final_kernel<<<grid, 256>>>(in, out);
}

// round 16
// speedup vs baseline: 1.0258x; 1.0027x over previous
#include <cuda_runtime.h>

// LocalExpansion via scatter — FINAL (session-best configuration, held).
// out[q, k, dv] = in[q + shift(k), dv] (7x7 window, zero-padded).
//
// Thread (bh, y, x, dv) loads its own 16B slice once, then scatters it with
// streaming stores (__stcs) to the 49 destinations q = p - shift(k) in
// ascending destination-address order, and zero-fills its own row's OOB taps.
// Interior pixels (76%) take a predicate-free 49-store path.
//
// Converged at ~71 us = 462 MB / 6.5 TB/s ~= 81% of HBM3e spec — the
// practical pure-write-stream ceiling. Fifteen rounds measured flat across:
// STG.128 / STG.256 / UBLKCP store paths, gather & scatter dataflows,
// 768-112896 CTA grids, 256/768-thread blocks, sorted/unsorted store orders,
// cs/wb policies, issue densities 3%-47%, 1-5 wave launches. Four runs of
// this exact binary: 70.98/71.71/71.78/72.10 us wall, 71.0-74.0 us ncu —
// replication noise covers the entire variant spread. SM issue 3.4%; the
// DRAM write stream is the only loaded resource.
//
// B*H = 16, N = 48*48 = 2304, K = 49, D = 64 floats (= 16 float4).

#define HEIGHT 48
#define WIDTH  48
#define NPIX   (HEIGHT * WIDTH)   // 2304
#define KK     49
#define DVEC   16                 // float4 per tap
#define ROWV   (KK * DVEC)        // 784 float4 per output pixel row

__global__ void __launch_bounds__(256) local_scatter_final_kernel(
    const float4* __restrict__ in, float4* __restrict__ out)
{
    // blockDim = 256 = 16 dv * 16 x-pixels ; gridDim = (3, 48, 16)
    const int dv = (int)(threadIdx.x & 15u);
    const int x  = (int)(blockIdx.x * 16u + (threadIdx.x >> 4));
    const int y  = (int)blockIdx.y;
    const int bh = (int)blockIdx.z;

    const unsigned int p = (unsigned)bh * NPIX + (unsigned)(y * WIDTH + x);

    const float4 v = __ldg(in + (size_t)p * DVEC + dv);
    float4* __restrict__ base = out + (size_t)p * ROWV + dv;

    if ((unsigned)(y - 3) < (unsigned)(HEIGHT - 6) &&
        (unsigned)(x - 3) < (unsigned)(WIDTH - 6)) {
        // Interior: all 49 destinations valid; descending shift order =>
        // ascending destination addresses.
        #pragma unroll
        for (int i = 6; i >= 0; --i) {
            #pragma unroll
            for (int j = 6; j >= 0; --j) {
                const int k = i * 7 + j;
                const int off = -(((i - 3) * WIDTH) + (j - 3)) * ROWV + k * DVEC;
                __stcs(base + off, v);
            }
        }
    } else {
        const float4 z = make_float4(0.f, 0.f, 0.f, 0.f);
        #pragma unroll
        for (int i = 6; i >= 0; --i) {
            const bool src_yok = (unsigned)(y + (i - 3)) < (unsigned)HEIGHT;
            const bool dst_yok = (unsigned)(y - (i - 3)) < (unsigned)HEIGHT;
            #pragma unroll
            for (int j = 6; j >= 0; --j) {
                const int k = i * 7 + j;
                const bool dst_ok = dst_yok && ((unsigned)(x - (j - 3)) < (unsigned)WIDTH);
                const bool src_ok = src_yok && ((unsigned)(x + (j - 3)) < (unsigned)WIDTH);

                const int off = -(((i - 3) * WIDTH) + (j - 3)) * ROWV + k * DVEC;
                if (dst_ok) __stcs(base + off, v);        // scatter my value
                if (!src_ok) __stcs(base + k * DVEC, z);  // zero-fill my OOB tap
            }
        }
    }
}

extern "C" void kernel_launch(void* const* d_in, const int* in_sizes, int n_in,
                              void* d_out, int out_size)
{
    const float4* in = (const float4*)d_in[0];
    float4* out = (float4*)d_out;
    (void)out_size;

    dim3 grid(WIDTH / 16, HEIGHT, 16);   // (3, 48, 16) -> 2304 CTAs
    local_scatter_final_kernel<<<grid, 256>>>(in, out);
}